// round 1
// baseline (speedup 1.0000x reference)
#include <cuda_runtime.h>

#define NRANGES 256
#define KPR     512
#define DOP     64
#define EMB     16
#define FIN     96
#define NTOT    (NRANGES * KPR)

#define PROJ_THREADS 256
#define SX_STRIDE    97   // pad 96 -> 97 to kill 32-way bank conflicts
#define ATTN_THREADS 512

// Global scratch (allocation-free rule: __device__ arrays)
__device__ float g_Q[(size_t)NTOT * DOP];
__device__ float g_K[(size_t)NTOT * DOP];
__device__ float g_vs[NTOT];

// ---------------------------------------------------------------------------
// Kernel 1: fused gather + Q/K projection + vsum
//   x[n] = [power_vals[n,0:64] | ele_table[ele[n]] | azi_table[azi[n]]]  (96)
//   Q[n] = x Wq^T + bq ; K[n] = x Wk^T + bk
//   vs[n] = x . (sum_d Wv[d,:]) + sum_d bv[d]
// ---------------------------------------------------------------------------
__global__ void __launch_bounds__(PROJ_THREADS)
proj_kernel(const float* __restrict__ pv,
            const int*   __restrict__ ele,
            const int*   __restrict__ azi,
            const float* __restrict__ ele_t,
            const float* __restrict__ azi_t,
            const float* __restrict__ Wq, const float* __restrict__ bq,
            const float* __restrict__ Wk, const float* __restrict__ bk,
            const float* __restrict__ Wv, const float* __restrict__ bv)
{
    extern __shared__ float sm[];
    float* sWq = sm;                    // [FIN*DOP], transposed: sWq[f*DOP+d]
    float* sWk = sWq + FIN * DOP;       // [FIN*DOP]
    float* swv = sWk + FIN * DOP;       // [FIN]  column sums of Wv
    float* sbq = swv + FIN;             // [DOP]
    float* sbk = sbq + DOP;             // [DOP]
    float* sbv = sbk + DOP;             // [1]
    float* sx  = sbv + 1;               // [PROJ_THREADS * SX_STRIDE]

    const int tid = threadIdx.x;

    // Stage transposed weights (broadcast-friendly f-major layout)
    for (int i = tid; i < FIN * DOP; i += PROJ_THREADS) {
        int d = i / FIN, f = i - d * FIN;
        sWq[f * DOP + d] = Wq[i];
        sWk[f * DOP + d] = Wk[i];
    }
    if (tid < FIN) {
        float s = 0.f;
        #pragma unroll
        for (int d = 0; d < DOP; ++d) s += Wv[d * FIN + tid];
        swv[tid] = s;
    }
    if (tid >= 128 && tid < 128 + DOP) sbq[tid - 128] = bq[tid - 128];
    if (tid >= 192 && tid < 192 + DOP) sbk[tid - 192] = bk[tid - 192];
    if (tid == 96) {
        float s = 0.f;
        for (int d = 0; d < DOP; ++d) s += bv[d];
        sbv[0] = s;
    }

    // Gather this thread's input row into padded smem
    const int n = blockIdx.x * PROJ_THREADS + tid;
    float* sxr = sx + tid * SX_STRIDE;
    {
        const float4* p4 = (const float4*)(pv + (size_t)n * DOP);
        #pragma unroll
        for (int j = 0; j < DOP / 4; ++j) {
            float4 v = p4[j];
            sxr[4*j] = v.x; sxr[4*j+1] = v.y; sxr[4*j+2] = v.z; sxr[4*j+3] = v.w;
        }
        int ei = ele[n], ai = azi[n];
        const float4* e4 = (const float4*)(ele_t + ei * EMB);
        const float4* a4 = (const float4*)(azi_t + ai * EMB);
        #pragma unroll
        for (int j = 0; j < EMB / 4; ++j) {
            float4 v = e4[j];
            sxr[DOP + 4*j] = v.x; sxr[DOP + 4*j+1] = v.y;
            sxr[DOP + 4*j+2] = v.z; sxr[DOP + 4*j+3] = v.w;
            float4 w = a4[j];
            sxr[DOP+EMB + 4*j] = w.x; sxr[DOP+EMB + 4*j+1] = w.y;
            sxr[DOP+EMB + 4*j+2] = w.z; sxr[DOP+EMB + 4*j+3] = w.w;
        }
    }
    __syncthreads();

    // vsum = x . wv_colsum + bv_sum
    {
        float s = sbv[0];
        #pragma unroll 8
        for (int f = 0; f < FIN; ++f) s += sxr[f] * swv[f];
        g_vs[n] = s;
    }

    // Q and K rows, 8 output dims per pass
    float* qout = g_Q + (size_t)n * DOP;
    float* kout = g_K + (size_t)n * DOP;
    for (int d0 = 0; d0 < DOP; d0 += 8) {
        float aq[8], ak[8];
        #pragma unroll
        for (int j = 0; j < 8; ++j) { aq[j] = sbq[d0 + j]; ak[j] = sbk[d0 + j]; }
        #pragma unroll 8
        for (int f = 0; f < FIN; ++f) {
            float xf = sxr[f];
            const float4* wq4 = (const float4*)(sWq + f * DOP + d0);
            const float4* wk4 = (const float4*)(sWk + f * DOP + d0);
            float4 q0 = wq4[0], q1 = wq4[1];
            float4 k0 = wk4[0], k1 = wk4[1];
            aq[0] += xf * q0.x; aq[1] += xf * q0.y; aq[2] += xf * q0.z; aq[3] += xf * q0.w;
            aq[4] += xf * q1.x; aq[5] += xf * q1.y; aq[6] += xf * q1.z; aq[7] += xf * q1.w;
            ak[0] += xf * k0.x; ak[1] += xf * k0.y; ak[2] += xf * k0.z; ak[3] += xf * k0.w;
            ak[4] += xf * k1.x; ak[5] += xf * k1.y; ak[6] += xf * k1.z; ak[7] += xf * k1.w;
        }
        ((float4*)(qout + d0))[0] = make_float4(aq[0], aq[1], aq[2], aq[3]);
        ((float4*)(qout + d0))[1] = make_float4(aq[4], aq[5], aq[6], aq[7]);
        ((float4*)(kout + d0))[0] = make_float4(ak[0], ak[1], ak[2], ak[3]);
        ((float4*)(kout + d0))[1] = make_float4(ak[4], ak[5], ak[6], ak[7]);
    }
}

// ---------------------------------------------------------------------------
// Kernel 2: per-range attention. 1 CTA = 1 range; thread q owns one query row.
//   out[r,q] = sum_k exp(Q[q].K[k]/8) * vs[k] / sum_k exp(Q[q].K[k]/8)
// (max-subtraction skipped: scores are O(1), exp is safe in fp32; softmax is
//  shift-invariant so the result matches the reference.)
// ---------------------------------------------------------------------------
__global__ void __launch_bounds__(ATTN_THREADS)
attn_kernel(float* __restrict__ out)
{
    extern __shared__ float sm[];
    float* Ks = sm;                 // [KPR * DOP]
    float* vs = Ks + KPR * DOP;     // [KPR]

    const int r = blockIdx.x;
    const int tid = threadIdx.x;

    // Cooperative load of this range's K tile + vsum
    {
        float4* Ks4 = (float4*)Ks;
        const float4* Kg4 = (const float4*)(g_K + (size_t)r * KPR * DOP);
        #pragma unroll
        for (int i = tid; i < KPR * DOP / 4; i += ATTN_THREADS) Ks4[i] = Kg4[i];
        vs[tid] = g_vs[r * KPR + tid];
    }
    __syncthreads();

    const int n = r * KPR + tid;
    float q[DOP];
    {
        const float4* q4 = (const float4*)(g_Q + (size_t)n * DOP);
        #pragma unroll
        for (int j = 0; j < DOP / 4; ++j) {
            float4 v = q4[j];
            q[4*j] = v.x; q[4*j+1] = v.y; q[4*j+2] = v.z; q[4*j+3] = v.w;
        }
    }

    float num = 0.f, den = 0.f;
    #pragma unroll 2
    for (int k = 0; k < KPR; ++k) {
        const float4* kr = (const float4*)(Ks + k * DOP);
        float s0 = 0.f, s1 = 0.f, s2 = 0.f, s3 = 0.f;
        #pragma unroll
        for (int j = 0; j < DOP / 4; ++j) {
            float4 kv = kr[j];
            s0 += q[4*j]     * kv.x;
            s1 += q[4*j + 1] * kv.y;
            s2 += q[4*j + 2] * kv.z;
            s3 += q[4*j + 3] * kv.w;
        }
        float s = ((s0 + s1) + (s2 + s3)) * 0.125f;
        float p = __expf(s);
        den += p;
        num += p * vs[k];
    }
    out[n] = num / den;
}

// ---------------------------------------------------------------------------
extern "C" void kernel_launch(void* const* d_in, const int* in_sizes, int n_in,
                              void* d_out, int out_size)
{
    const float* pv    = (const float*)d_in[0];
    const int*   ele   = (const int*)  d_in[1];
    // d_in[2] = range_indices: unused by the reference computation
    const int*   azi   = (const int*)  d_in[3];
    const float* ele_t = (const float*)d_in[4];
    const float* azi_t = (const float*)d_in[5];
    const float* Wq    = (const float*)d_in[6];
    const float* bq    = (const float*)d_in[7];
    const float* Wk    = (const float*)d_in[8];
    const float* bk    = (const float*)d_in[9];
    const float* Wv    = (const float*)d_in[10];
    const float* bv    = (const float*)d_in[11];
    float* out = (float*)d_out;

    const int proj_smem = (2 * FIN * DOP + FIN + 2 * DOP + 1 +
                           PROJ_THREADS * SX_STRIDE) * (int)sizeof(float);
    const int attn_smem = (KPR * DOP + KPR) * (int)sizeof(float);

    cudaFuncSetAttribute(proj_kernel, cudaFuncAttributeMaxDynamicSharedMemorySize, proj_smem);
    cudaFuncSetAttribute(attn_kernel, cudaFuncAttributeMaxDynamicSharedMemorySize, attn_smem);

    proj_kernel<<<NTOT / PROJ_THREADS, PROJ_THREADS, proj_smem>>>(
        pv, ele, azi, ele_t, azi_t, Wq, bq, Wk, bk, Wv, bv);
    attn_kernel<<<NRANGES, ATTN_THREADS, attn_smem>>>(out);
}

// round 4
// speedup vs baseline: 1.0282x; 1.0282x over previous
#include <cuda_runtime.h>

#define NRANGES 256
#define KPR     512
#define DOP     64
#define EMB     16
#define FIN     96
#define NTOT    (NRANGES * KPR)

#define PROJ_THREADS 256
#define SX_STRIDE    97   // pad 96 -> 97 to kill bank conflicts
#define ATTN_THREADS 512

// Global scratch (allocation-free rule: __device__ arrays)
__device__ float g_Q[(size_t)NTOT * DOP];
__device__ float g_K[(size_t)NTOT * DOP];
__device__ float g_vs[NTOT];

// ---- packed fp32x2 helpers (sm_103a FFMA2 path, ptxas won't auto-fuse) ----
__device__ __forceinline__ void fma2(unsigned long long& d,
                                     unsigned long long a,
                                     unsigned long long b) {
    asm("fma.rn.f32x2 %0, %1, %2, %0;" : "+l"(d) : "l"(a), "l"(b));
}
__device__ __forceinline__ void add2(unsigned long long& d,
                                     unsigned long long a) {
    asm("add.rn.f32x2 %0, %0, %1;" : "+l"(d) : "l"(a));
}
__device__ __forceinline__ unsigned long long splat2(float x) {
    unsigned long long r;
    asm("mov.b64 %0, {%1, %1};" : "=l"(r) : "f"(x));
    return r;
}
__device__ __forceinline__ float lo2(unsigned long long v) {
    return __uint_as_float((unsigned int)v);
}
__device__ __forceinline__ float hi2(unsigned long long v) {
    return __uint_as_float((unsigned int)(v >> 32));
}

// ---------------------------------------------------------------------------
// Kernel 1: fused gather + Q/K projection + vsum (packed f32x2 math)
// ---------------------------------------------------------------------------
__global__ void __launch_bounds__(PROJ_THREADS)
proj_kernel(const float* __restrict__ pv,
            const int*   __restrict__ ele,
            const int*   __restrict__ azi,
            const float* __restrict__ ele_t,
            const float* __restrict__ azi_t,
            const float* __restrict__ Wq, const float* __restrict__ bq,
            const float* __restrict__ Wk, const float* __restrict__ bk,
            const float* __restrict__ Wv, const float* __restrict__ bv)
{
    extern __shared__ float sm[];
    float* sWq = sm;                    // [FIN*DOP], transposed: sWq[f*DOP+d]
    float* sWk = sWq + FIN * DOP;       // [FIN*DOP]
    float* swv = sWk + FIN * DOP;       // [FIN]  column sums of Wv
    float* sbq = swv + FIN;             // [DOP]
    float* sbk = sbq + DOP;             // [DOP]
    float* sbv = sbk + DOP;             // [2] (keep even for alignment)
    float* sx  = sbv + 2;               // [PROJ_THREADS * SX_STRIDE]

    const int tid = threadIdx.x;

    // Stage transposed weights (broadcast-friendly f-major layout)
    for (int i = tid; i < FIN * DOP; i += PROJ_THREADS) {
        int d = i / FIN, f = i - d * FIN;
        sWq[f * DOP + d] = Wq[i];
        sWk[f * DOP + d] = Wk[i];
    }
    if (tid < FIN) {
        float s = 0.f;
        #pragma unroll
        for (int d = 0; d < DOP; ++d) s += Wv[d * FIN + tid];
        swv[tid] = s;
    }
    if (tid >= 128 && tid < 128 + DOP) sbq[tid - 128] = bq[tid - 128];
    if (tid >= 192 && tid < 192 + DOP) sbk[tid - 192] = bk[tid - 192];
    if (tid == 96) {
        float s = 0.f;
        for (int d = 0; d < DOP; ++d) s += bv[d];
        sbv[0] = s;
    }

    // Gather this thread's input row into padded smem
    const int n = blockIdx.x * PROJ_THREADS + tid;
    float* sxr = sx + tid * SX_STRIDE;
    {
        const float4* p4 = (const float4*)(pv + (size_t)n * DOP);
        #pragma unroll
        for (int j = 0; j < DOP / 4; ++j) {
            float4 v = p4[j];
            sxr[4*j] = v.x; sxr[4*j+1] = v.y; sxr[4*j+2] = v.z; sxr[4*j+3] = v.w;
        }
        int ei = ele[n], ai = azi[n];
        const float4* e4 = (const float4*)(ele_t + ei * EMB);
        const float4* a4 = (const float4*)(azi_t + ai * EMB);
        #pragma unroll
        for (int j = 0; j < EMB / 4; ++j) {
            float4 v = e4[j];
            sxr[DOP + 4*j] = v.x; sxr[DOP + 4*j+1] = v.y;
            sxr[DOP + 4*j+2] = v.z; sxr[DOP + 4*j+3] = v.w;
            float4 w = a4[j];
            sxr[DOP+EMB + 4*j] = w.x; sxr[DOP+EMB + 4*j+1] = w.y;
            sxr[DOP+EMB + 4*j+2] = w.z; sxr[DOP+EMB + 4*j+3] = w.w;
        }
    }
    __syncthreads();

    // vsum = x . wv_colsum + bv_sum
    {
        float s = sbv[0];
        #pragma unroll 8
        for (int f = 0; f < FIN; ++f) s += sxr[f] * swv[f];
        g_vs[n] = s;
    }

    // Q and K rows: 32 output dims per pass, packed f32x2 accumulators
    float* qout = g_Q + (size_t)n * DOP;
    float* kout = g_K + (size_t)n * DOP;
    #pragma unroll
    for (int d0 = 0; d0 < DOP; d0 += 32) {
        unsigned long long aq[16], ak[16];
        const unsigned long long* bq2 = (const unsigned long long*)(sbq + d0);
        const unsigned long long* bk2 = (const unsigned long long*)(sbk + d0);
        #pragma unroll
        for (int j = 0; j < 16; ++j) { aq[j] = bq2[j]; ak[j] = bk2[j]; }

        #pragma unroll 4
        for (int f = 0; f < FIN; ++f) {
            unsigned long long xp = splat2(sxr[f]);
            const ulonglong2* wq2 = (const ulonglong2*)(sWq + f * DOP + d0);
            const ulonglong2* wk2 = (const ulonglong2*)(sWk + f * DOP + d0);
            #pragma unroll
            for (int j = 0; j < 8; ++j) {
                ulonglong2 wq = wq2[j];
                fma2(aq[2*j],   xp, wq.x);
                fma2(aq[2*j+1], xp, wq.y);
            }
            #pragma unroll
            for (int j = 0; j < 8; ++j) {
                ulonglong2 wk = wk2[j];
                fma2(ak[2*j],   xp, wk.x);
                fma2(ak[2*j+1], xp, wk.y);
            }
        }
        unsigned long long* q2 = (unsigned long long*)(qout + d0);
        unsigned long long* k2 = (unsigned long long*)(kout + d0);
        #pragma unroll
        for (int j = 0; j < 16; ++j) { q2[j] = aq[j]; k2[j] = ak[j]; }
    }
}

// ---------------------------------------------------------------------------
// Kernel 2: per-range attention, packed f32x2 dot products.
//   out[r,q] = sum_k exp(Q[q].K[k]/8) * vs[k] / sum_k exp(Q[q].K[k]/8)
// (max-subtraction skipped: scores are O(1); softmax shift-invariant.)
// ---------------------------------------------------------------------------
__global__ void __launch_bounds__(ATTN_THREADS)
attn_kernel(float* __restrict__ out)
{
    extern __shared__ float sm[];
    float* Ks = sm;                 // [KPR * DOP]
    float* vs = Ks + KPR * DOP;     // [KPR]

    const int r = blockIdx.x;
    const int tid = threadIdx.x;

    // Cooperative load of this range's K tile + vsum
    {
        float4* Ks4 = (float4*)Ks;
        const float4* Kg4 = (const float4*)(g_K + (size_t)r * KPR * DOP);
        #pragma unroll
        for (int i = tid; i < KPR * DOP / 4; i += ATTN_THREADS) Ks4[i] = Kg4[i];
        vs[tid] = g_vs[r * KPR + tid];
    }
    __syncthreads();

    const int n = r * KPR + tid;

    // Q row in registers, already in packed-pair form (32 x f32x2)
    unsigned long long qp[DOP / 2];
    {
        const ulonglong2* q2 = (const ulonglong2*)(g_Q + (size_t)n * DOP);
        #pragma unroll
        for (int j = 0; j < DOP / 4; ++j) {
            ulonglong2 v = q2[j];
            qp[2*j] = v.x; qp[2*j+1] = v.y;
        }
    }

    float num = 0.f, den = 0.f;
    #pragma unroll 2
    for (int k = 0; k < KPR; ++k) {
        const ulonglong2* kr = (const ulonglong2*)(Ks + k * DOP);
        unsigned long long a0 = 0, a1 = 0, a2 = 0, a3 = 0;
        #pragma unroll
        for (int j = 0; j < DOP / 4; j += 2) {
            ulonglong2 kv0 = kr[j];
            ulonglong2 kv1 = kr[j + 1];
            fma2(a0, qp[2*j],     kv0.x);
            fma2(a1, qp[2*j + 1], kv0.y);
            fma2(a2, qp[2*j + 2], kv1.x);
            fma2(a3, qp[2*j + 3], kv1.y);
        }
        add2(a0, a2);
        add2(a1, a3);
        add2(a0, a1);
        float s = (lo2(a0) + hi2(a0)) * 0.125f;
        float p = __expf(s);
        den += p;
        num += p * vs[k];
    }
    out[n] = num / den;
}

// ---------------------------------------------------------------------------
extern "C" void kernel_launch(void* const* d_in, const int* in_sizes, int n_in,
                              void* d_out, int out_size)
{
    const float* pv    = (const float*)d_in[0];
    const int*   ele   = (const int*)  d_in[1];
    // d_in[2] = range_indices: unused by the reference computation
    const int*   azi   = (const int*)  d_in[3];
    const float* ele_t = (const float*)d_in[4];
    const float* azi_t = (const float*)d_in[5];
    const float* Wq    = (const float*)d_in[6];
    const float* bq    = (const float*)d_in[7];
    const float* Wk    = (const float*)d_in[8];
    const float* bk    = (const float*)d_in[9];
    const float* Wv    = (const float*)d_in[10];
    const float* bv    = (const float*)d_in[11];
    float* out = (float*)d_out;

    const int proj_smem = (2 * FIN * DOP + FIN + 2 * DOP + 2 +
                           PROJ_THREADS * SX_STRIDE) * (int)sizeof(float);
    const int attn_smem = (KPR * DOP + KPR) * (int)sizeof(float);

    cudaFuncSetAttribute(proj_kernel, cudaFuncAttributeMaxDynamicSharedMemorySize, proj_smem);
    cudaFuncSetAttribute(attn_kernel, cudaFuncAttributeMaxDynamicSharedMemorySize, attn_smem);

    proj_kernel<<<NTOT / PROJ_THREADS, PROJ_THREADS, proj_smem>>>(
        pv, ele, azi, ele_t, azi_t, Wq, bq, Wk, bk, Wv, bv);
    attn_kernel<<<NRANGES, ATTN_THREADS, attn_smem>>>(out);
}

// round 8
// speedup vs baseline: 1.5863x; 1.5428x over previous
#include <cuda_runtime.h>

#define NRANGES 256
#define KPR     512
#define DOP     64
#define EMB     16
#define FIN     96
#define NTOT    (NRANGES * KPR)

#define PROJ_THREADS 256
#define PROJ_ROWS    128       // rows per proj CTA
#define OCOLS        128       // fused output cols: [Q 0:64 | K 64:128]
#define SWP          132       // padded f-row stride (keeps 16B alignment: 132*4=528, 528%16==0)

#define ATTN_THREADS 256       // each thread owns 2 q rows

// Global scratch (allocation-free rule: __device__ arrays)
__device__ __align__(256) float g_QK[(size_t)NTOT * OCOLS];  // [n][0:64]=Q, [64:128]=K
__device__ __align__(256) float g_vs[NTOT];

// ---- packed fp32x2 helpers (sm_103a FFMA2 path, ptxas won't auto-fuse) ----
__device__ __forceinline__ void fma2(unsigned long long& d,
                                     unsigned long long a,
                                     unsigned long long b) {
    asm("fma.rn.f32x2 %0, %1, %2, %0;" : "+l"(d) : "l"(a), "l"(b));
}
__device__ __forceinline__ void add2(unsigned long long& d,
                                     unsigned long long a) {
    asm("add.rn.f32x2 %0, %0, %1;" : "+l"(d) : "l"(a));
}
__device__ __forceinline__ unsigned long long splat2(float x) {
    unsigned long long r;
    asm("mov.b64 %0, {%1, %1};" : "=l"(r) : "f"(x));
    return r;
}
__device__ __forceinline__ float lo2(unsigned long long v) {
    return __uint_as_float((unsigned int)v);
}
__device__ __forceinline__ float hi2(unsigned long long v) {
    return __uint_as_float((unsigned int)(v >> 32));
}

// ---------------------------------------------------------------------------
// Kernel 1: fused gather + QK projection + vsum, GEMM register tiling.
//   C[128 rows][128 cols] += X[128][96] * W'[96][128],  W' = [Wq^T | Wk^T]
//   Thread tile: 8 rows x 8 cols (cols packed as 4 f32x2 accumulators/row).
// ---------------------------------------------------------------------------
__global__ void __launch_bounds__(PROJ_THREADS)
proj_kernel(const float* __restrict__ pv,
            const int*   __restrict__ ele,
            const int*   __restrict__ azi,
            const float* __restrict__ ele_t,
            const float* __restrict__ azi_t,
            const float* __restrict__ Wq, const float* __restrict__ bq,
            const float* __restrict__ Wk, const float* __restrict__ bk,
            const float* __restrict__ Wv, const float* __restrict__ bv)
{
    extern __shared__ float sm[];
    float* sW    = sm;                    // [FIN][SWP]  W'[f][d']
    float* sX    = sW + FIN * SWP;        // [FIN][SWP]  X^T[f][row]
    float* sbias = sX + FIN * SWP;        // [128] = [bq | bk]
    float* swv   = sbias + OCOLS;         // [FIN] colsums of Wv
    float* sbv   = swv + FIN;             // [2]

    const int tid = threadIdx.x;
    const int n0  = blockIdx.x * PROJ_ROWS;

    // ---- stage W' (coalesced gmem; 4-way STS conflict is negligible) ----
    for (int i = tid; i < 64 * FIN; i += PROJ_THREADS) {
        int d = i / FIN, f = i - d * FIN;
        sW[f * SWP + d]      = Wq[i];
        sW[f * SWP + 64 + d] = Wk[i];
    }
    if (tid < 64)            sbias[tid]      = bq[tid];
    else if (tid < 128)      sbias[tid]      = bk[tid - 64];
    if (tid < FIN) {
        float s = 0.f;
        #pragma unroll
        for (int d = 0; d < DOP; ++d) s += Wv[d * FIN + tid];
        swv[tid] = s;
    }
    if (tid == 128) {
        float s = 0.f;
        for (int d = 0; d < DOP; ++d) s += bv[d];
        sbv[0] = s;
    }

    // ---- stage X^T: row 'row' handled by 2 threads (halves of 48 features) ----
    {
        const int half = tid >> 7;        // 0/1
        const int row  = tid & 127;
        const int n    = n0 + row;
        float* dst = sX + row;
        if (half == 0) {
            const float4* p4 = (const float4*)(pv + (size_t)n * DOP);
            #pragma unroll
            for (int j = 0; j < 12; ++j) {           // f = 0..47
                float4 v = p4[j];
                dst[(4*j+0) * SWP] = v.x; dst[(4*j+1) * SWP] = v.y;
                dst[(4*j+2) * SWP] = v.z; dst[(4*j+3) * SWP] = v.w;
            }
        } else {
            const float4* p4 = (const float4*)(pv + (size_t)n * DOP);
            #pragma unroll
            for (int j = 12; j < 16; ++j) {          // f = 48..63
                float4 v = p4[j];
                dst[(4*j+0) * SWP] = v.x; dst[(4*j+1) * SWP] = v.y;
                dst[(4*j+2) * SWP] = v.z; dst[(4*j+3) * SWP] = v.w;
            }
            const int ei = ele[n], ai = azi[n];
            const float4* e4 = (const float4*)(ele_t + ei * EMB);
            const float4* a4 = (const float4*)(azi_t + ai * EMB);
            #pragma unroll
            for (int j = 0; j < 4; ++j) {            // f = 64..79, 80..95
                float4 v = e4[j];
                dst[(DOP + 4*j+0) * SWP] = v.x; dst[(DOP + 4*j+1) * SWP] = v.y;
                dst[(DOP + 4*j+2) * SWP] = v.z; dst[(DOP + 4*j+3) * SWP] = v.w;
                float4 w = a4[j];
                dst[(DOP+EMB + 4*j+0) * SWP] = w.x; dst[(DOP+EMB + 4*j+1) * SWP] = w.y;
                dst[(DOP+EMB + 4*j+2) * SWP] = w.z; dst[(DOP+EMB + 4*j+3) * SWP] = w.w;
            }
        }
    }
    __syncthreads();

    // ---- main GEMM: thread (tr, tc) owns rows 8*tr..+7, cols 8*tc..+7 ----
    const int tc = tid & 15;
    const int tr = tid >> 4;

    unsigned long long acc[8][4];
    {
        const unsigned long long* bp = (const unsigned long long*)(sbias + 8 * tc);
        #pragma unroll
        for (int r = 0; r < 8; ++r)
            #pragma unroll
            for (int c = 0; c < 4; ++c) acc[r][c] = bp[c];
    }

    #pragma unroll 4
    for (int f = 0; f < FIN; ++f) {
        const float* xr = sX + f * SWP + 8 * tr;
        float4 xa = *(const float4*)xr;
        float4 xb = *(const float4*)(xr + 4);
        const ulonglong2* wp = (const ulonglong2*)(sW + f * SWP + 8 * tc);
        ulonglong2 w0 = wp[0], w1 = wp[1];
        unsigned long long xs[8];
        xs[0] = splat2(xa.x); xs[1] = splat2(xa.y);
        xs[2] = splat2(xa.z); xs[3] = splat2(xa.w);
        xs[4] = splat2(xb.x); xs[5] = splat2(xb.y);
        xs[6] = splat2(xb.z); xs[7] = splat2(xb.w);
        #pragma unroll
        for (int r = 0; r < 8; ++r) {
            fma2(acc[r][0], xs[r], w0.x);
            fma2(acc[r][1], xs[r], w0.y);
            fma2(acc[r][2], xs[r], w1.x);
            fma2(acc[r][3], xs[r], w1.y);
        }
    }

    // ---- store 8x8 tile ----
    #pragma unroll
    for (int r = 0; r < 8; ++r) {
        float* outp = g_QK + (size_t)(n0 + 8 * tr + r) * OCOLS + 8 * tc;
        ulonglong2 v0, v1;
        v0.x = acc[r][0]; v0.y = acc[r][1];
        v1.x = acc[r][2]; v1.y = acc[r][3];
        ((ulonglong2*)outp)[0] = v0;
        ((ulonglong2*)outp)[1] = v1;
    }

    // ---- vsum for this CTA's 128 rows ----
    if (tid < PROJ_ROWS) {
        const int row = tid;
        float s = sbv[0];
        #pragma unroll 8
        for (int f = 0; f < FIN; ++f) s += sX[f * SWP + row] * swv[f];
        g_vs[n0 + row] = s;
    }
}

// ---------------------------------------------------------------------------
// Kernel 2: per-range attention; thread owns q rows {tid, tid+256}.
//   out[r,q] = sum_k exp(Q[q].K[k]/8) * vs[k] / sum_k exp(Q[q].K[k]/8)
// (max-subtraction skipped: scores are O(1); softmax shift-invariant.)
// ---------------------------------------------------------------------------
__global__ void __launch_bounds__(ATTN_THREADS)
attn_kernel(float* __restrict__ out)
{
    extern __shared__ float sm[];
    float* Ks = sm;                 // [KPR][DOP]
    float* vs = Ks + KPR * DOP;     // [KPR]

    const int r = blockIdx.x;
    const int tid = threadIdx.x;

    // Cooperative load of this range's K tile (g_QK cols 64:128) + vsum
    {
        float4* Ks4 = (float4*)Ks;
        const float* Kg = g_QK + (size_t)r * KPR * OCOLS + DOP;
        for (int i = tid; i < KPR * (DOP / 4); i += ATTN_THREADS) {
            int krow = i >> 4, chunk = i & 15;
            Ks4[krow * (DOP / 4) + chunk] =
                ((const float4*)(Kg + (size_t)krow * OCOLS))[chunk];
        }
        vs[tid]       = g_vs[r * KPR + tid];
        vs[tid + 256] = g_vs[r * KPR + tid + 256];
    }
    __syncthreads();

    const int n1 = r * KPR + tid;
    const int n2 = n1 + 256;

    // Two Q rows in registers (packed f32x2 pairs)
    unsigned long long qa[DOP / 2], qb[DOP / 2];
    {
        const ulonglong2* q2a = (const ulonglong2*)(g_QK + (size_t)n1 * OCOLS);
        const ulonglong2* q2b = (const ulonglong2*)(g_QK + (size_t)n2 * OCOLS);
        #pragma unroll
        for (int j = 0; j < DOP / 4; ++j) {
            ulonglong2 va = q2a[j];
            qa[2*j] = va.x; qa[2*j+1] = va.y;
            ulonglong2 vb = q2b[j];
            qb[2*j] = vb.x; qb[2*j+1] = vb.y;
        }
    }

    float num1 = 0.f, den1 = 0.f, num2 = 0.f, den2 = 0.f;
    #pragma unroll 2
    for (int k = 0; k < KPR; ++k) {
        const ulonglong2* kr = (const ulonglong2*)(Ks + k * DOP);
        unsigned long long a0 = 0, a1 = 0, a2 = 0, a3 = 0;
        unsigned long long b0 = 0, b1 = 0, b2 = 0, b3 = 0;
        #pragma unroll
        for (int j = 0; j < DOP / 4; j += 2) {
            ulonglong2 kv0 = kr[j];
            ulonglong2 kv1 = kr[j + 1];
            fma2(a0, qa[2*j],     kv0.x);
            fma2(a1, qa[2*j + 1], kv0.y);
            fma2(a2, qa[2*j + 2], kv1.x);
            fma2(a3, qa[2*j + 3], kv1.y);
            fma2(b0, qb[2*j],     kv0.x);
            fma2(b1, qb[2*j + 1], kv0.y);
            fma2(b2, qb[2*j + 2], kv1.x);
            fma2(b3, qb[2*j + 3], kv1.y);
        }
        add2(a0, a2); add2(a1, a3); add2(a0, a1);
        add2(b0, b2); add2(b1, b3); add2(b0, b1);
        float vk = vs[k];
        float s1 = (lo2(a0) + hi2(a0)) * 0.125f;
        float s2 = (lo2(b0) + hi2(b0)) * 0.125f;
        float p1 = __expf(s1);
        float p2 = __expf(s2);
        den1 += p1; num1 = fmaf(p1, vk, num1);
        den2 += p2; num2 = fmaf(p2, vk, num2);
    }
    out[n1] = num1 / den1;
    out[n2] = num2 / den2;
}

// ---------------------------------------------------------------------------
extern "C" void kernel_launch(void* const* d_in, const int* in_sizes, int n_in,
                              void* d_out, int out_size)
{
    const float* pv    = (const float*)d_in[0];
    const int*   ele   = (const int*)  d_in[1];
    // d_in[2] = range_indices: unused by the reference computation
    const int*   azi   = (const int*)  d_in[3];
    const float* ele_t = (const float*)d_in[4];
    const float* azi_t = (const float*)d_in[5];
    const float* Wq    = (const float*)d_in[6];
    const float* bq    = (const float*)d_in[7];
    const float* Wk    = (const float*)d_in[8];
    const float* bk    = (const float*)d_in[9];
    const float* Wv    = (const float*)d_in[10];
    const float* bv    = (const float*)d_in[11];
    float* out = (float*)d_out;

    const int proj_smem = (2 * FIN * SWP + OCOLS + FIN + 2) * (int)sizeof(float);
    const int attn_smem = (KPR * DOP + KPR) * (int)sizeof(float);

    cudaFuncSetAttribute(proj_kernel, cudaFuncAttributeMaxDynamicSharedMemorySize, proj_smem);
    cudaFuncSetAttribute(attn_kernel, cudaFuncAttributeMaxDynamicSharedMemorySize, attn_smem);

    proj_kernel<<<NTOT / PROJ_ROWS, PROJ_THREADS, proj_smem>>>(
        pv, ele, azi, ele_t, azi_t, Wq, bq, Wk, bk, Wv, bv);
    attn_kernel<<<NRANGES, ATTN_THREADS, attn_smem>>>(out);
}

// round 12
// speedup vs baseline: 3.0160x; 1.9012x over previous
#include <cuda_runtime.h>
#include <cuda_bf16.h>
#include <cstdint>

#define NRANGES 256
#define KPR     512
#define DOP     64
#define EMB     16
#define FIN     96
#define NTOT    (NRANGES * KPR)

#define PROJ_THREADS 256
#define PROJ_ROWS    128
#define OCOLS        128
#define SWP          132

#define ATTN_THREADS 512           // 16 warps x 32 q-rows
#define KROW_STRIDE  144           // 36 words; 36 mod 32 == 4 -> conflict-free B frags
#define SM_VS        0             // 512 floats
#define SM_KH        2048
#define SM_KL        (SM_KH + KPR * KROW_STRIDE)    // 2048 + 73728
#define SM_ATTN      (SM_KL + KPR * KROW_STRIDE)    // 149504 bytes

// ---- global scratch (allocation-free rule) ----
__device__ __align__(256) __nv_bfloat16 g_Qh[(size_t)NTOT * DOP];  // Q/8 hi
__device__ __align__(256) __nv_bfloat16 g_Ql[(size_t)NTOT * DOP];  // Q/8 lo
__device__ __align__(256) __nv_bfloat16 g_Kh[(size_t)NTOT * DOP];  // K hi
__device__ __align__(256) __nv_bfloat16 g_Kl[(size_t)NTOT * DOP];  // K lo
__device__ __align__(256) float         g_vs[NTOT];

// ---- packed fp32x2 helpers ----
__device__ __forceinline__ void fma2(unsigned long long& d,
                                     unsigned long long a,
                                     unsigned long long b) {
    asm("fma.rn.f32x2 %0, %1, %2, %0;" : "+l"(d) : "l"(a), "l"(b));
}
__device__ __forceinline__ unsigned long long splat2(float x) {
    unsigned long long r;
    asm("mov.b64 %0, {%1, %1};" : "=l"(r) : "f"(x));
    return r;
}
__device__ __forceinline__ float lo2(unsigned long long v) {
    return __uint_as_float((unsigned int)v);
}
__device__ __forceinline__ float hi2(unsigned long long v) {
    return __uint_as_float((unsigned int)(v >> 32));
}

// ---- mma.sync m16n8k16 bf16 (baseline PTX, no sm_103a feature gate) ----
#define MMA16816(C, A, B) \
    asm volatile("mma.sync.aligned.m16n8k16.row.col.f32.bf16.bf16.f32 " \
                 "{%0,%1,%2,%3}, {%4,%5,%6,%7}, {%8,%9}, {%0,%1,%2,%3};" \
                 : "+f"((C)[0]), "+f"((C)[1]), "+f"((C)[2]), "+f"((C)[3]) \
                 : "r"((A)[0]), "r"((A)[1]), "r"((A)[2]), "r"((A)[3]), \
                   "r"((B)[0]), "r"((B)[1]))

// ---------------------------------------------------------------------------
// Kernel 1: fused gather + QK projection + vsum, GEMM register tiling.
// Emits Q/8 and K as bf16 hi/lo split pairs (row-major [n][64]).
// ---------------------------------------------------------------------------
__global__ void __launch_bounds__(PROJ_THREADS)
proj_kernel(const float* __restrict__ pv,
            const int*   __restrict__ ele,
            const int*   __restrict__ azi,
            const float* __restrict__ ele_t,
            const float* __restrict__ azi_t,
            const float* __restrict__ Wq, const float* __restrict__ bq,
            const float* __restrict__ Wk, const float* __restrict__ bk,
            const float* __restrict__ Wv, const float* __restrict__ bv)
{
    extern __shared__ float sm[];
    float* sW    = sm;                    // [FIN][SWP]  W'[f][d']  (d'<64: Q, >=64: K)
    float* sX    = sW + FIN * SWP;        // [FIN][SWP]  X^T[f][row]
    float* sbias = sX + FIN * SWP;        // [128] = [bq | bk]
    float* swv   = sbias + OCOLS;         // [FIN]
    float* sbv   = swv + FIN;             // [2]

    const int tid = threadIdx.x;
    const int n0  = blockIdx.x * PROJ_ROWS;

    for (int i = tid; i < 64 * FIN; i += PROJ_THREADS) {
        int d = i / FIN, f = i - d * FIN;
        sW[f * SWP + d]      = Wq[i];
        sW[f * SWP + 64 + d] = Wk[i];
    }
    if (tid < 64)            sbias[tid] = bq[tid];
    else if (tid < 128)      sbias[tid] = bk[tid - 64];
    if (tid < FIN) {
        float s = 0.f;
        #pragma unroll
        for (int d = 0; d < DOP; ++d) s += Wv[d * FIN + tid];
        swv[tid] = s;
    }
    if (tid == 128) {
        float s = 0.f;
        for (int d = 0; d < DOP; ++d) s += bv[d];
        sbv[0] = s;
    }

    // stage X^T (2 threads per row)
    {
        const int half = tid >> 7;
        const int row  = tid & 127;
        const int n    = n0 + row;
        float* dst = sX + row;
        if (half == 0) {
            const float4* p4 = (const float4*)(pv + (size_t)n * DOP);
            #pragma unroll
            for (int j = 0; j < 12; ++j) {
                float4 v = p4[j];
                dst[(4*j+0) * SWP] = v.x; dst[(4*j+1) * SWP] = v.y;
                dst[(4*j+2) * SWP] = v.z; dst[(4*j+3) * SWP] = v.w;
            }
        } else {
            const float4* p4 = (const float4*)(pv + (size_t)n * DOP);
            #pragma unroll
            for (int j = 12; j < 16; ++j) {
                float4 v = p4[j];
                dst[(4*j+0) * SWP] = v.x; dst[(4*j+1) * SWP] = v.y;
                dst[(4*j+2) * SWP] = v.z; dst[(4*j+3) * SWP] = v.w;
            }
            const int ei = ele[n], ai = azi[n];
            const float4* e4 = (const float4*)(ele_t + ei * EMB);
            const float4* a4 = (const float4*)(azi_t + ai * EMB);
            #pragma unroll
            for (int j = 0; j < 4; ++j) {
                float4 v = e4[j];
                dst[(DOP + 4*j+0) * SWP] = v.x; dst[(DOP + 4*j+1) * SWP] = v.y;
                dst[(DOP + 4*j+2) * SWP] = v.z; dst[(DOP + 4*j+3) * SWP] = v.w;
                float4 w = a4[j];
                dst[(DOP+EMB + 4*j+0) * SWP] = w.x; dst[(DOP+EMB + 4*j+1) * SWP] = w.y;
                dst[(DOP+EMB + 4*j+2) * SWP] = w.z; dst[(DOP+EMB + 4*j+3) * SWP] = w.w;
            }
        }
    }
    __syncthreads();

    const int tc = tid & 15;
    const int tr = tid >> 4;

    unsigned long long acc[8][4];
    {
        const unsigned long long* bp = (const unsigned long long*)(sbias + 8 * tc);
        #pragma unroll
        for (int r = 0; r < 8; ++r)
            #pragma unroll
            for (int c = 0; c < 4; ++c) acc[r][c] = bp[c];
    }

    #pragma unroll 4
    for (int f = 0; f < FIN; ++f) {
        const float* xr = sX + f * SWP + 8 * tr;
        float4 xa = *(const float4*)xr;
        float4 xb = *(const float4*)(xr + 4);
        const ulonglong2* wp = (const ulonglong2*)(sW + f * SWP + 8 * tc);
        ulonglong2 w0 = wp[0], w1 = wp[1];
        unsigned long long xs[8];
        xs[0] = splat2(xa.x); xs[1] = splat2(xa.y);
        xs[2] = splat2(xa.z); xs[3] = splat2(xa.w);
        xs[4] = splat2(xb.x); xs[5] = splat2(xb.y);
        xs[6] = splat2(xb.z); xs[7] = splat2(xb.w);
        #pragma unroll
        for (int r = 0; r < 8; ++r) {
            fma2(acc[r][0], xs[r], w0.x);
            fma2(acc[r][1], xs[r], w0.y);
            fma2(acc[r][2], xs[r], w1.x);
            fma2(acc[r][3], xs[r], w1.y);
        }
    }

    // ---- store 8x8 tile as bf16 hi/lo (Q scaled by 1/8) ----
    const bool isQ = (tc < 8);
    const float oscale = isQ ? 0.125f : 1.0f;
    __nv_bfloat16* dst_h = isQ ? g_Qh : g_Kh;
    __nv_bfloat16* dst_l = isQ ? g_Ql : g_Kl;
    const int col0 = (8 * tc) & 63;
    #pragma unroll
    for (int r = 0; r < 8; ++r) {
        float v[8];
        v[0] = lo2(acc[r][0]); v[1] = hi2(acc[r][0]);
        v[2] = lo2(acc[r][1]); v[3] = hi2(acc[r][1]);
        v[4] = lo2(acc[r][2]); v[5] = hi2(acc[r][2]);
        v[6] = lo2(acc[r][3]); v[7] = hi2(acc[r][3]);
        unsigned int hp[4], lp[4];
        #pragma unroll
        for (int c = 0; c < 4; ++c) {
            float x0 = v[2*c]   * oscale;
            float x1 = v[2*c+1] * oscale;
            __nv_bfloat16 h0 = __float2bfloat16_rn(x0);
            __nv_bfloat16 h1 = __float2bfloat16_rn(x1);
            __nv_bfloat16 l0 = __float2bfloat16_rn(x0 - __bfloat162float(h0));
            __nv_bfloat16 l1 = __float2bfloat16_rn(x1 - __bfloat162float(h1));
            hp[c] = (unsigned int)__bfloat16_as_ushort(h0) |
                    ((unsigned int)__bfloat16_as_ushort(h1) << 16);
            lp[c] = (unsigned int)__bfloat16_as_ushort(l0) |
                    ((unsigned int)__bfloat16_as_ushort(l1) << 16);
        }
        size_t off = (size_t)(n0 + 8 * tr + r) * DOP + col0;
        *(uint4*)(dst_h + off) = make_uint4(hp[0], hp[1], hp[2], hp[3]);
        *(uint4*)(dst_l + off) = make_uint4(lp[0], lp[1], lp[2], lp[3]);
    }

    if (tid < PROJ_ROWS) {
        const int row = tid;
        float s = sbv[0];
        #pragma unroll 8
        for (int f = 0; f < FIN; ++f) s += sX[f * SWP + row] * swv[f];
        g_vs[n0 + row] = s;
    }
}

// ---------------------------------------------------------------------------
// Kernel 2: HMMA attention. 1 CTA = 1 range; warp w owns q-rows w*32..w*32+31.
//   S = Qh.Kh^T + Ql.Kh^T + Qh.Kl^T  (fp32 accum, mma.sync m16n8k16 bf16)
//   p = expf(S) (Q pre-scaled 1/8), out = sum(p*vs)/sum(p)
// Fragment layouts (canonical m16n8k16): plain 32-bit loads from row-major
// [row][64]bf16 tiles; K smem row stride 36 words -> B-frag banks = 4g+t
// (conflict-free for both b0 and b1).
// ---------------------------------------------------------------------------
__global__ void __launch_bounds__(ATTN_THREADS, 1)
attn_kernel(float* __restrict__ out)
{
    extern __shared__ char smem[];
    float* vsm = (float*)(smem + SM_VS);

    const int tid  = threadIdx.x;
    const int wid  = tid >> 5;
    const int lane = tid & 31;
    const int g    = lane >> 2;
    const int t    = lane & 3;
    const int r    = blockIdx.x;

    // ---- stage K hi/lo + vs ----
    {
        const uint4* khg = (const uint4*)(g_Kh + (size_t)r * KPR * DOP);
        const uint4* klg = (const uint4*)(g_Kl + (size_t)r * KPR * DOP);
        for (int i = tid; i < KPR * 8; i += ATTN_THREADS) {
            int row = i >> 3, c = i & 7;
            *(uint4*)(smem + SM_KH + row * KROW_STRIDE + c * 16) = khg[i];
            *(uint4*)(smem + SM_KL + row * KROW_STRIDE + c * 16) = klg[i];
        }
        if (tid < KPR) vsm[tid] = g_vs[r * KPR + tid];
    }
    __syncthreads();

    // ---- Q fragments (persist in registers), loaded straight from gmem ----
    const int m0 = wid * 32;
    const uint32_t* qhg = (const uint32_t*)g_Qh + ((size_t)r * KPR + m0) * 32;
    const uint32_t* qlg = (const uint32_t*)g_Ql + ((size_t)r * KPR + m0) * 32;
    uint32_t qh[2][4][4], ql[2][4][4];
    #pragma unroll
    for (int mt = 0; mt < 2; ++mt) {
        const int row0 = mt * 16 + g;
        #pragma unroll
        for (int ks = 0; ks < 4; ++ks) {
            const int w0 = 8 * ks + t, w1 = w0 + 4;
            qh[mt][ks][0] = qhg[row0 * 32 + w0];
            qh[mt][ks][1] = qhg[(row0 + 8) * 32 + w0];
            qh[mt][ks][2] = qhg[row0 * 32 + w1];
            qh[mt][ks][3] = qhg[(row0 + 8) * 32 + w1];
            ql[mt][ks][0] = qlg[row0 * 32 + w0];
            ql[mt][ks][1] = qlg[(row0 + 8) * 32 + w0];
            ql[mt][ks][2] = qlg[row0 * 32 + w1];
            ql[mt][ks][3] = qlg[(row0 + 8) * 32 + w1];
        }
    }

    float num[4] = {0.f, 0.f, 0.f, 0.f};
    float den[4] = {0.f, 0.f, 0.f, 0.f};

    #pragma unroll 1
    for (int nb = 0; nb < KPR / 8; ++nb) {
        const int n0 = nb * 8;
        const char* rowh = smem + SM_KH + (n0 + g) * KROW_STRIDE + t * 4;
        const char* rowl = smem + SM_KL + (n0 + g) * KROW_STRIDE + t * 4;

        uint32_t b[4][2];
        #pragma unroll
        for (int ks = 0; ks < 4; ++ks) {
            b[ks][0] = *(const uint32_t*)(rowh + ks * 32);
            b[ks][1] = *(const uint32_t*)(rowh + ks * 32 + 16);
        }

        float C[2][4] = {{0.f,0.f,0.f,0.f},{0.f,0.f,0.f,0.f}};
        #pragma unroll
        for (int mt = 0; mt < 2; ++mt) {
            #pragma unroll
            for (int ks = 0; ks < 4; ++ks) MMA16816(C[mt], qh[mt][ks], b[ks]);
            #pragma unroll
            for (int ks = 0; ks < 4; ++ks) MMA16816(C[mt], ql[mt][ks], b[ks]);
        }

        #pragma unroll
        for (int ks = 0; ks < 4; ++ks) {
            b[ks][0] = *(const uint32_t*)(rowl + ks * 32);
            b[ks][1] = *(const uint32_t*)(rowl + ks * 32 + 16);
        }
        #pragma unroll
        for (int mt = 0; mt < 2; ++mt) {
            #pragma unroll
            for (int ks = 0; ks < 4; ++ks) MMA16816(C[mt], qh[mt][ks], b[ks]);
        }

        // epilogue for these 8 key-columns
        const float2 vv = *(const float2*)(vsm + n0 + 2 * t);
        #pragma unroll
        for (int mt = 0; mt < 2; ++mt) {
            float p0 = __expf(C[mt][0]);
            float p1 = __expf(C[mt][1]);
            float p2 = __expf(C[mt][2]);
            float p3 = __expf(C[mt][3]);
            den[2*mt]   += p0 + p1;
            num[2*mt]    = fmaf(p0, vv.x, fmaf(p1, vv.y, num[2*mt]));
            den[2*mt+1] += p2 + p3;
            num[2*mt+1]  = fmaf(p2, vv.x, fmaf(p3, vv.y, num[2*mt+1]));
        }
    }

    // quad reduction across t (lanes xor 1, 2 share the same row g)
    #pragma unroll
    for (int j = 0; j < 4; ++j) {
        num[j] += __shfl_xor_sync(0xffffffffu, num[j], 1);
        den[j] += __shfl_xor_sync(0xffffffffu, den[j], 1);
        num[j] += __shfl_xor_sync(0xffffffffu, num[j], 2);
        den[j] += __shfl_xor_sync(0xffffffffu, den[j], 2);
    }
    if (t == 0) {
        #pragma unroll
        for (int mt = 0; mt < 2; ++mt) {
            out[r * KPR + m0 + mt * 16 + g]     = num[2*mt]   / den[2*mt];
            out[r * KPR + m0 + mt * 16 + 8 + g] = num[2*mt+1] / den[2*mt+1];
        }
    }
}

// ---------------------------------------------------------------------------
extern "C" void kernel_launch(void* const* d_in, const int* in_sizes, int n_in,
                              void* d_out, int out_size)
{
    const float* pv    = (const float*)d_in[0];
    const int*   ele   = (const int*)  d_in[1];
    // d_in[2] = range_indices: unused by the reference computation
    const int*   azi   = (const int*)  d_in[3];
    const float* ele_t = (const float*)d_in[4];
    const float* azi_t = (const float*)d_in[5];
    const float* Wq    = (const float*)d_in[6];
    const float* bq    = (const float*)d_in[7];
    const float* Wk    = (const float*)d_in[8];
    const float* bk    = (const float*)d_in[9];
    const float* Wv    = (const float*)d_in[10];
    const float* bv    = (const float*)d_in[11];
    float* out = (float*)d_out;

    const int proj_smem = (2 * FIN * SWP + OCOLS + FIN + 2) * (int)sizeof(float);

    cudaFuncSetAttribute(proj_kernel, cudaFuncAttributeMaxDynamicSharedMemorySize, proj_smem);
    cudaFuncSetAttribute(attn_kernel, cudaFuncAttributeMaxDynamicSharedMemorySize, SM_ATTN);

    proj_kernel<<<NTOT / PROJ_ROWS, PROJ_THREADS, proj_smem>>>(
        pv, ele, azi, ele_t, azi_t, Wq, bq, Wk, bk, Wv, bv);
    attn_kernel<<<NRANGES, ATTN_THREADS, SM_ATTN>>>(out);
}